// round 3
// baseline (speedup 1.0000x reference)
#include <cuda_runtime.h>
#include <cuda_bf16.h>

// Bidirectional linear RNN (units=1, linear, no bias), B=T=4096, scalar k,r.
//   fw_t = k*x_t + r*fw_{t-1};  bw_t = k*x_t + r*bw_{t+1}
// d_out = [stateless (B*T*2) | diff (B*T*2 zeros)], fw/bw interleaved.
//
// One block per row (grid 4096, 256 threads, 16 elems/thread in regs).
// Chunk multiplier q=r^16 uniform -> warp shfl scan + 8-aggregate fold.
// smem: ONE 4480-float buffer reused: x row (pad 1/16), then output staging
// in two half-row rounds (pad 1/32). While one half of the threads stages,
// the other half streams zeros to the diff row, so global stores issue in
// every phase. Target 6 CTAs/SM via __launch_bounds__(256, 6).

#define BB      4096
#define TT      4096
#define THREADS 256
#define CHUNK   16
#define NWARP   (THREADS / 32)

__global__ __launch_bounds__(THREADS, 6) void birnn_kernel(
    const float* __restrict__ x,
    const float* __restrict__ kp,
    const float* __restrict__ rp,
    float* __restrict__ out)
{
    __shared__ float sbuf[4480];   // x: 4352 used (pad 1/16); staging: 4224 (pad 1/32)
    __shared__ float Af[NWARP];
    __shared__ float Ab[NWARP];

    const int b    = blockIdx.x;
    const int tid  = threadIdx.x;
    const int lane = tid & 31;
    const int w    = tid >> 5;
    const float k  = *kp;
    const float r  = *rp;

    // q = r^16, Q = q^32
    float q = r * r; q = q * q; q = q * q; q = q * q;
    float Q = q;
    #pragma unroll
    for (int i = 0; i < 5; i++) Q = Q * Q;

    // ---- Load row into padded smem (coalesced; keep x L2-resident: no ldcs)
    const float4* xrow = (const float4*)(x + (size_t)b * TT);
    #pragma unroll
    for (int i = tid; i < TT / 4; i += THREADS) {
        float4 v = xrow[i];
        int idx = 4 * i;
        int p = idx + (idx >> 4);
        sbuf[p + 0] = v.x; sbuf[p + 1] = v.y;
        sbuf[p + 2] = v.z; sbuf[p + 3] = v.w;
    }
    __syncthreads();                                   // B1

    // ---- My 16 consecutive elements (stride 17, conflict-free)
    float xv[CHUNK];
    {
        int p = tid * 17;
        #pragma unroll
        for (int j = 0; j < CHUNK; j++) xv[j] = sbuf[p + j];
    }

    // ---- Local chunk scans from zero state
    float bL = 0.f, bR = 0.f;
    #pragma unroll
    for (int j = 0; j < CHUNK; j++) bL = fmaf(r, bL, k * xv[j]);
    #pragma unroll
    for (int j = CHUNK - 1; j >= 0; j--) bR = fmaf(r, bR, k * xv[j]);

    // ---- Warp shfl scans (factor q): fw ascending / bw descending
    float vf = bL, vb = bR, qd = q;
    #pragma unroll
    for (int d = 1; d < 32; d <<= 1) {
        float of = __shfl_up_sync(0xffffffffu, vf, d);
        float ob = __shfl_down_sync(0xffffffffu, vb, d);
        if (lane >= d)     vf = fmaf(qd, of, vf);
        if (lane + d < 32) vb = fmaf(qd, ob, vb);
        qd *= qd;
    }
    if (lane == 31) Af[w] = vf;
    if (lane == 0)  Ab[w] = vb;
    __syncthreads();                                   // B2 (also: x reads done)

    // ---- Fold warp aggregates (factor Q) -> exclusive prefixes
    float Ef = 0.f;
    #pragma unroll
    for (int u = 0; u < NWARP; u++)
        if (u < w) Ef = fmaf(Q, Ef, Af[u]);
    float Eb = 0.f;
    #pragma unroll
    for (int u = NWARP - 1; u >= 0; u--)
        if (u > w) Eb = fmaf(Q, Eb, Ab[u]);

    // q^lane and q^(31-lane)
    float pwf = 1.f, pwb = 1.f, t = q;
    #pragma unroll
    for (int bit = 0; bit < 5; bit++) {
        if (lane & (1 << bit))        pwf *= t;
        if ((31 - lane) & (1 << bit)) pwb *= t;
        t *= t;
    }

    float hfp = __shfl_up_sync(0xffffffffu, vf, 1);
    float hbn = __shfl_down_sync(0xffffffffu, vb, 1);
    const float seedF = (lane > 0)  ? fmaf(pwf, Ef, hfp) : Ef;
    const float seedB = (lane < 31) ? fmaf(pwb, Eb, hbn) : Eb;

    // ---- Two half-row rounds: stage + write, with zero-fill on idle threads
    float4* orow = (float4*)(out + (size_t)b * (2 * TT));
    float4* drow = (float4*)(out + (size_t)BB * TT * 2 + (size_t)b * (2 * TT));
    const float4 z4 = make_float4(0.f, 0.f, 0.f, 0.f);

    #pragma unroll
    for (int half = 0; half < 2; half++) {
        const int lo = half * (THREADS / 2);           // staging threads [lo, lo+128)
        if ((tid >> 7) == half) {
            // stage my 16 (fw,bw) pairs at stride 33 (conflict-free)
            int p = (tid - lo) * 33;
            float h = seedF;
            #pragma unroll
            for (int j = 0; j < CHUNK; j++) {
                h = fmaf(r, h, k * xv[j]);
                sbuf[p + 2 * j] = h;
            }
            float hb = seedB;
            #pragma unroll
            for (int j = CHUNK - 1; j >= 0; j--) {
                hb = fmaf(r, hb, k * xv[j]);
                sbuf[p + 2 * j + 1] = hb;
            }
        } else {
            // other half streams zeros to this half of the diff row
            int base = half * 1024 + (tid & 127) * 8;  // 128 thr x 8 float4
            #pragma unroll
            for (int j = 0; j < 8; j++)
                __stcs(drow + base + j, z4);
        }
        __syncthreads();
        // all 256 threads write this half of the stateless row (1024 float4)
        int m = half * 1024 + tid;
        #pragma unroll
        for (int rgn = 0; rgn < 4; rgn++, m += THREADS) {
            int idx = 4 * (m - half * 1024);
            int p = idx + (idx >> 5);
            float4 v = make_float4(sbuf[p], sbuf[p + 1], sbuf[p + 2], sbuf[p + 3]);
            __stcs(orow + m, v);
        }
        if (half == 0) __syncthreads();
    }
}

extern "C" void kernel_launch(void* const* d_in, const int* in_sizes, int n_in,
                              void* d_out, int out_size)
{
    const float* x  = (const float*)d_in[0];
    const float* kp = (const float*)d_in[1];
    const float* rp = (const float*)d_in[2];
    float* out = (float*)d_out;
    birnn_kernel<<<BB, THREADS>>>(x, kp, rp, out);
}

// round 5
// speedup vs baseline: 1.2324x; 1.2324x over previous
#include <cuda_runtime.h>
#include <cuda_bf16.h>

// Bidirectional linear RNN (units=1, linear, no bias), B=T=4096, scalar k,r.
//   fw_t = k*x_t + r*fw_{t-1};  bw_t = k*x_t + r*bw_{t+1}
// d_out = [stateless (B*T*2) | diff (B*T*2 zeros)], fw/bw interleaved.
//
// Grid 6144, interleaved 2:1 -> 4096 RNN blocks + 2048 zero-fill blocks.
// RNN block: 256 thr x 16 elems in regs; q=r^16 uniform -> warp shfl scan +
// 8-aggregate fold. Epilogue is PER-WARP: each warp stages its 1024 outputs
// in its own padded smem region and writes its own coalesced span after a
// __syncwarp -- only 2 block-wide barriers total. Zero blocks: pure
// coalesced streaming stcs. 6 CTAs/SM via __launch_bounds__(256, 6).

#define BB      4096
#define TT      4096
#define THREADS 256
#define CHUNK   16
#define NWARP   (THREADS / 32)
#define WSPAN   1056   // 1024 output floats + 32 pad per warp region

__global__ __launch_bounds__(THREADS, 6) void birnn_kernel(
    const float* __restrict__ x,
    const float* __restrict__ kp,
    const float* __restrict__ rp,
    float* __restrict__ out)
{
    __shared__ float sbuf[NWARP * WSPAN];   // 8448: x row (pad 1/16) then per-warp staging
    __shared__ float Af[NWARP];
    __shared__ float Ab[NWARP];

    const int z   = blockIdx.x;
    const int m3  = z % 3;
    const int tid = threadIdx.x;

    float* const diffBase = out + (size_t)BB * TT * 2;

    if (m3 == 2) {
        // ---------- pure streaming zero-fill block (coalesced) ----------
        const int seg = z / 3;                      // 0..2047
        float4* dst = (float4*)diffBase + (size_t)seg * 4096;
        const float4 z4 = make_float4(0.f, 0.f, 0.f, 0.f);
        #pragma unroll 4
        for (int m = tid; m < 4096; m += THREADS)
            __stcs(dst + m, z4);
        return;
    }

    // ---------- RNN block ----------
    const int b    = (z / 3) * 2 + m3;              // row 0..4095
    const int lane = tid & 31;
    const int w    = tid >> 5;
    const float k  = *kp;
    const float r  = *rp;

    // q = r^16, Q = q^32
    float q = r * r; q = q * q; q = q * q; q = q * q;
    float Q = q;
    #pragma unroll
    for (int i = 0; i < 5; i++) Q = Q * Q;

    // ---- Coalesced load of row into padded smem (keep x L2-resident)
    const float4* xrow = (const float4*)(x + (size_t)b * TT);
    #pragma unroll
    for (int i = tid; i < TT / 4; i += THREADS) {
        float4 v = xrow[i];
        int idx = 4 * i;
        int p = idx + (idx >> 4);
        sbuf[p + 0] = v.x; sbuf[p + 1] = v.y;
        sbuf[p + 2] = v.z; sbuf[p + 3] = v.w;
    }
    __syncthreads();                                 // B1

    // ---- My 16 consecutive elements (stride 17, conflict-free)
    float xv[CHUNK];
    {
        int p = tid * 17;
        #pragma unroll
        for (int j = 0; j < CHUNK; j++) xv[j] = sbuf[p + j];
    }

    // ---- Local chunk scans from zero state
    float bL = 0.f, bR = 0.f;
    #pragma unroll
    for (int j = 0; j < CHUNK; j++) bL = fmaf(r, bL, k * xv[j]);
    #pragma unroll
    for (int j = CHUNK - 1; j >= 0; j--) bR = fmaf(r, bR, k * xv[j]);

    // ---- Warp shfl scans (factor q): fw ascending / bw descending
    float vf = bL, vb = bR, qd = q;
    #pragma unroll
    for (int d = 1; d < 32; d <<= 1) {
        float of = __shfl_up_sync(0xffffffffu, vf, d);
        float ob = __shfl_down_sync(0xffffffffu, vb, d);
        if (lane >= d)     vf = fmaf(qd, of, vf);
        if (lane + d < 32) vb = fmaf(qd, ob, vb);
        qd *= qd;
    }
    if (lane == 31) Af[w] = vf;
    if (lane == 0)  Ab[w] = vb;
    __syncthreads();                                 // B2 (x reads done too)

    // ---- Fold warp aggregates (factor Q) -> exclusive prefixes
    float Ef = 0.f;
    #pragma unroll
    for (int u = 0; u < NWARP; u++)
        if (u < w) Ef = fmaf(Q, Ef, Af[u]);
    float Eb = 0.f;
    #pragma unroll
    for (int u = NWARP - 1; u >= 0; u--)
        if (u > w) Eb = fmaf(Q, Eb, Ab[u]);

    // q^lane and q^(31-lane)
    float pwf = 1.f, pwb = 1.f, t = q;
    #pragma unroll
    for (int bit = 0; bit < 5; bit++) {
        if (lane & (1 << bit))        pwf *= t;
        if ((31 - lane) & (1 << bit)) pwb *= t;
        t *= t;
    }

    float hfp = __shfl_up_sync(0xffffffffu, vf, 1);
    float hbn = __shfl_down_sync(0xffffffffu, vb, 1);
    const float seedF = (lane > 0)  ? fmaf(pwf, Ef, hfp) : Ef;
    const float seedB = (lane < 31) ? fmaf(pwb, Eb, hbn) : Eb;

    // ---- Per-warp epilogue: stage 32 floats/lane, syncwarp, write 1KB span
    const int R = w * WSPAN;
    {
        int p = R + lane * 33;                       // banks = lane, conflict-free
        float h = seedF;
        #pragma unroll
        for (int j = 0; j < CHUNK; j++) {
            h = fmaf(r, h, k * xv[j]);
            sbuf[p + 2 * j] = h;
        }
        float hb = seedB;
        #pragma unroll
        for (int j = CHUNK - 1; j >= 0; j--) {
            hb = fmaf(r, hb, k * xv[j]);
            sbuf[p + 2 * j + 1] = hb;
        }
    }
    __syncwarp();

    // warp w owns out4[b][w*256 .. w*256+255]
    float4* orow = (float4*)(out + (size_t)b * (2 * TT));
    #pragma unroll
    for (int it = 0; it < 8; it++) {
        int idx = 128 * it + 4 * lane;               // word offset in warp span
        int p = R + idx + (idx >> 5);                // conflict-free permutation
        float4 v = make_float4(sbuf[p], sbuf[p + 1], sbuf[p + 2], sbuf[p + 3]);
        __stcs(orow + w * 256 + it * 32 + lane, v);
    }
}

extern "C" void kernel_launch(void* const* d_in, const int* in_sizes, int n_in,
                              void* d_out, int out_size)
{
    const float* x  = (const float*)d_in[0];
    const float* kp = (const float*)d_in[1];
    const float* rp = (const float*)d_in[2];
    float* out = (float*)d_out;
    birnn_kernel<<<BB + BB / 2, THREADS>>>(x, kp, rp, out);
}

// round 6
// speedup vs baseline: 1.2381x; 1.0046x over previous
#include <cuda_runtime.h>
#include <cuda_bf16.h>

// Bidirectional linear RNN (units=1, linear, no bias), B=T=4096, scalar k,r.
//   fw_t = k*x_t + r*fw_{t-1};  bw_t = k*x_t + r*bw_{t+1}
// d_out = [stateless (B*T*2) | diff (B*T*2 zeros)], fw/bw interleaved.
//
// One block per row (grid 4096, 256 thr, 16 elems/thread in regs).
// q = r^16 uniform -> warp shfl scan + 8-aggregate fold (2 block barriers).
// The row's diff zero-fill (2048 float4, coalesced grid-stride) is fused
// into phase A, interleaved with the x loads: zero stores issue during the
// load-latency window, keeping the store stream busy end-to-end.

#define BB      4096
#define TT      4096
#define THREADS 256
#define CHUNK   16
#define NWARP   (THREADS / 32)

__global__ __launch_bounds__(THREADS, 6) void birnn_kernel(
    const float* __restrict__ x,
    const float* __restrict__ kp,
    const float* __restrict__ rp,
    float* __restrict__ out)
{
    __shared__ float sbuf[8448];    // x (pad 1/16: 4352 used), staging (pad 1/32: 8448)
    __shared__ float Af[NWARP];
    __shared__ float Ab[NWARP];

    const int b    = blockIdx.x;
    const int tid  = threadIdx.x;
    const int lane = tid & 31;
    const int w    = tid >> 5;
    const float k  = *kp;
    const float r  = *rp;

    // q = r^16, Q = q^32
    float q = r * r; q = q * q; q = q * q; q = q * q;
    float Q = q;
    #pragma unroll
    for (int i = 0; i < 5; i++) Q = Q * Q;

    // ---- Phase A: x load into padded smem + fused coalesced diff zero-fill
    const float4* xrow = (const float4*)(x + (size_t)b * TT);
    float4*       drow = (float4*)(out + (size_t)BB * TT * 2 + (size_t)b * (2 * TT));
    const float4  z4   = make_float4(0.f, 0.f, 0.f, 0.f);
    #pragma unroll
    for (int i = 0; i < 4; i++) {
        int ix = tid + i * THREADS;                   // 0..1023, coalesced
        float4 v = xrow[ix];
        __stcs(drow + tid + (2 * i) * THREADS, z4);   // coalesced zero stores,
        __stcs(drow + tid + (2 * i + 1) * THREADS, z4); // issued under load latency
        int idx = 4 * ix;
        int p = idx + (idx >> 4);
        sbuf[p + 0] = v.x; sbuf[p + 1] = v.y;
        sbuf[p + 2] = v.z; sbuf[p + 3] = v.w;
    }
    __syncthreads();                                  // B1

    // ---- My 16 consecutive elements (stride 17, conflict-free)
    float xv[CHUNK];
    {
        int p = tid * 17;
        #pragma unroll
        for (int j = 0; j < CHUNK; j++) xv[j] = sbuf[p + j];
    }

    // ---- Local chunk scans from zero state
    float bL = 0.f, bR = 0.f;
    #pragma unroll
    for (int j = 0; j < CHUNK; j++) bL = fmaf(r, bL, k * xv[j]);
    #pragma unroll
    for (int j = CHUNK - 1; j >= 0; j--) bR = fmaf(r, bR, k * xv[j]);

    // ---- Warp shfl scans (factor q): fw ascending / bw descending
    float vf = bL, vb = bR, qd = q;
    #pragma unroll
    for (int d = 1; d < 32; d <<= 1) {
        float of = __shfl_up_sync(0xffffffffu, vf, d);
        float ob = __shfl_down_sync(0xffffffffu, vb, d);
        if (lane >= d)     vf = fmaf(qd, of, vf);
        if (lane + d < 32) vb = fmaf(qd, ob, vb);
        qd *= qd;
    }
    if (lane == 31) Af[w] = vf;
    if (lane == 0)  Ab[w] = vb;
    __syncthreads();                                  // B2 (x reads done too)

    // ---- Fold warp aggregates (factor Q) -> exclusive prefixes
    float Ef = 0.f;
    #pragma unroll
    for (int u = 0; u < NWARP; u++)
        if (u < w) Ef = fmaf(Q, Ef, Af[u]);
    float Eb = 0.f;
    #pragma unroll
    for (int u = NWARP - 1; u >= 0; u--)
        if (u > w) Eb = fmaf(Q, Eb, Ab[u]);

    // q^lane and q^(31-lane)
    float pwf = 1.f, pwb = 1.f, t = q;
    #pragma unroll
    for (int bit = 0; bit < 5; bit++) {
        if (lane & (1 << bit))        pwf *= t;
        if ((31 - lane) & (1 << bit)) pwb *= t;
        t *= t;
    }

    float hfp = __shfl_up_sync(0xffffffffu, vf, 1);
    float hbn = __shfl_down_sync(0xffffffffu, vb, 1);
    const float seedF = (lane > 0)  ? fmaf(pwf, Ef, hfp) : Ef;
    const float seedB = (lane < 31) ? fmaf(pwb, Eb, hbn) : Eb;

    // ---- Stage interleaved (fw,bw) pairs at stride 33 (conflict-free)
    {
        int p = tid * 33;
        float h = seedF;
        #pragma unroll
        for (int j = 0; j < CHUNK; j++) {
            h = fmaf(r, h, k * xv[j]);
            sbuf[p + 2 * j] = h;
        }
        float hb = seedB;
        #pragma unroll
        for (int j = CHUNK - 1; j >= 0; j--) {
            hb = fmaf(r, hb, k * xv[j]);
            sbuf[p + 2 * j + 1] = hb;
        }
    }
    __syncthreads();                                  // B3

    // ---- Coalesced streaming writeback of the stateless row
    float4* orow = (float4*)(out + (size_t)b * (2 * TT));
    #pragma unroll
    for (int m = tid; m < (2 * TT) / 4; m += THREADS) {
        int idx = 4 * m;
        int p = idx + (idx >> 5);
        float4 v = make_float4(sbuf[p], sbuf[p + 1], sbuf[p + 2], sbuf[p + 3]);
        __stcs(orow + m, v);
    }
}

extern "C" void kernel_launch(void* const* d_in, const int* in_sizes, int n_in,
                              void* d_out, int out_size)
{
    const float* x  = (const float*)d_in[0];
    const float* kp = (const float*)d_in[1];
    const float* rp = (const float*)d_in[2];
    float* out = (float*)d_out;
    birnn_kernel<<<BB, THREADS>>>(x, kp, rp, out);
}